// round 16
// baseline (speedup 1.0000x reference)
#include <cuda_runtime.h>

// out[b,f] = x[b,f] * (log_sigma[f] < 1.0f ? e : 1.0f)
// BATCH=65536, N_FEATURES=4096 -> 2^26 float4. Pure HBM stream (2.15 GB).
//
// R16 (converged): champion mechanism — fine-grained launch, 1024-thread
// blocks, 2 front-batched independent 128-bit loads (32B/lane in flight =
// measured DRAM optimum, 89.1% / 7.06 TB/s; MLP1, MLP4, v8, coarse loops,
// cache hints, and locality re-pairing all measured worse or neutral) —
// with pure 32-bit index arithmetic (element indices < 2^26) to drop the
// IMAD.WIDE chains of the 64-bit versions.

#define N_FEATURES   4096
#define VEC4_PER_ROW (N_FEATURES / 4)            // 1024, power of two
#define TOTAL_VEC4   (1u << 26)                   // 2^26 float4

#define THREADS  1024u
#define BLOCKS   32768u                           // 2^25 threads total
#define NSTRIDE  (THREADS * BLOCKS)               // 2^25, multiple of 1024

__global__ void __launch_bounds__(THREADS)
svdropout2d_kernel(const float4* __restrict__ x,
                   const float4* __restrict__ log_sigma,
                   float4* __restrict__ out)
{
    const float E = 2.71828182845904523536f;

    const unsigned i = blockIdx.x * THREADS + threadIdx.x;   // < 2^25

    // Same column for both elements (NSTRIDE % 1024 == 0): one scale load.
    const unsigned c = i & (VEC4_PER_ROW - 1);
    const float4 ls = __ldg(&log_sigma[c]);

    float4 s;
    s.x = (ls.x < 1.0f) ? E : 1.0f;
    s.y = (ls.y < 1.0f) ? E : 1.0f;
    s.z = (ls.z < 1.0f) ? E : 1.0f;
    s.w = (ls.w < 1.0f) ? E : 1.0f;

    // Front-batched independent loads (MLP_p1 = 2, 32B/lane in flight)
    float4 v0 = x[i];
    float4 v1 = x[i + NSTRIDE];

    v0.x *= s.x; v0.y *= s.y; v0.z *= s.z; v0.w *= s.w;
    v1.x *= s.x; v1.y *= s.y; v1.z *= s.z; v1.w *= s.w;

    out[i]           = v0;
    out[i + NSTRIDE] = v1;
}

extern "C" void kernel_launch(void* const* d_in, const int* in_sizes, int n_in,
                              void* d_out, int out_size)
{
    const float4* x  = (const float4*)d_in[0];
    const float4* ls = (const float4*)d_in[1];
    float4* out      = (float4*)d_out;

    svdropout2d_kernel<<<BLOCKS, THREADS>>>(x, ls, out);
}

// round 17
// speedup vs baseline: 1.0017x; 1.0017x over previous
#include <cuda_runtime.h>

// out[b,f] = x[b,f] * (log_sigma[f] < 1.0f ? e : 1.0f)
// BATCH=65536, N_FEATURES=4096 -> 2^26 float4. Pure HBM stream (2.15 GB).
//
// R17 (final converged form): intersection of the two best variants —
//   * fine-grained launch, 1024-thread blocks (CTA-coarsening won 3x)
//   * 2 front-batched independent 128-bit loads (32B/lane in flight =
//     measured DRAM optimum: 89.4% / 7.09 TB/s; MLP1/MLP4/v8 all worse)
//   * 32-bit index arithmetic (R16: best device time, 295.5us)
//   * streaming evict-first hints on the zero-reuse x/out streams
//     (R13: best wall time, 302.9us); log_sigma stays cache-resident.
// All other axes (locality pairing, coarse loops, cache policy on MLP1,
// block 256/512, grid shape) measured neutral or worse across R1-R16.

#define N_FEATURES   4096
#define VEC4_PER_ROW (N_FEATURES / 4)            // 1024, power of two

#define THREADS  1024u
#define BLOCKS   32768u                           // 2^25 threads total
#define NSTRIDE  (THREADS * BLOCKS)               // 2^25, multiple of 1024

__global__ void __launch_bounds__(THREADS)
svdropout2d_kernel(const float4* __restrict__ x,
                   const float4* __restrict__ log_sigma,
                   float4* __restrict__ out)
{
    const float E = 2.71828182845904523536f;

    const unsigned i = blockIdx.x * THREADS + threadIdx.x;   // < 2^25

    // Same column for both elements (NSTRIDE % 1024 == 0): one scale load.
    const unsigned c = i & (VEC4_PER_ROW - 1);
    const float4 ls = __ldg(&log_sigma[c]);

    float4 s;
    s.x = (ls.x < 1.0f) ? E : 1.0f;
    s.y = (ls.y < 1.0f) ? E : 1.0f;
    s.z = (ls.z < 1.0f) ? E : 1.0f;
    s.w = (ls.w < 1.0f) ? E : 1.0f;

    // Front-batched independent loads (MLP_p1 = 2, 32B/lane in flight),
    // evict-first streaming policy.
    float4 v0 = __ldcs(&x[i]);
    float4 v1 = __ldcs(&x[i + NSTRIDE]);

    v0.x *= s.x; v0.y *= s.y; v0.z *= s.z; v0.w *= s.w;
    v1.x *= s.x; v1.y *= s.y; v1.z *= s.z; v1.w *= s.w;

    __stcs(&out[i],           v0);
    __stcs(&out[i + NSTRIDE], v1);
}

extern "C" void kernel_launch(void* const* d_in, const int* in_sizes, int n_in,
                              void* d_out, int out_size)
{
    const float4* x  = (const float4*)d_in[0];
    const float4* ls = (const float4*)d_in[1];
    float4* out      = (float4*)d_out;

    svdropout2d_kernel<<<BLOCKS, THREADS>>>(x, ls, out);
}